// round 13
// baseline (speedup 1.0000x reference)
#include <cuda_runtime.h>
#include <cuda_bf16.h>
#include <mma.h>
#include <math.h>
#include <stdint.h>

using namespace nvcuda;

#define Bdim 4096
#define Zdim 256
#define Ydim 64
#define Xdim 30000
#define Xpad 30080
#define NBT  32            // number of b-tiles (Bdim/128)
#define BN_EPS 1e-3f

// ---------------- device scratch ----------------
__device__ __nv_bfloat16 g_Ah[Bdim * Zdim], g_Al[Bdim * Zdim];   // zs*tmp_L
__device__ __nv_bfloat16 g_Wh[Xpad * Zdim], g_Wl[Xpad * Zdim];   // W_g2 (padded X)
__device__ float g_R[(size_t)Bdim * Xpad];                       // R = y @ style_R
__device__ float g_WmuT[Ydim * Zdim], g_WvarT[Ydim * Zdim];      // transposed [Y,Z]
__device__ float g_ps[NBT * Xpad], g_pq[NBT * Xpad];             // BN partial sums
__device__ float g_scale[Xdim], g_shift[Xdim];

__device__ __forceinline__ void bsplit(float v, __nv_bfloat16& h, __nv_bfloat16& l) {
    h = __float2bfloat16(v);
    l = __float2bfloat16(v - __bfloat162float(h));
}

__device__ __forceinline__ uint32_t smem_u32(const void* p) {
    uint32_t a;
    asm("{ .reg .u64 t; cvta.to.shared.u64 t, %1; cvt.u32.u64 %0, t; }" : "=r"(a) : "l"(p));
    return a;
}
#define CP_ASYNC16(dst, src) \
    asm volatile("cp.async.cg.shared.global [%0], [%1], 16;" :: "r"(dst), "l"(src))
#define CP_COMMIT() asm volatile("cp.async.commit_group;")
#define CP_WAIT1()  asm volatile("cp.async.wait_group 1;")
#define CP_WAIT0()  asm volatile("cp.async.wait_group 0;")

// ============================================================================
// Launch 1: k1R — R = y @ style_R (bf16x3), self-converting, -> g_R
// ============================================================================
#define RLDA 72
#define RLDB 136
#define R_YH 0
#define R_YL 18432
#define R_SH 36864
#define R_SL 54272
#define KR_SMEM 71680

__global__ __launch_bounds__(256, 2) void k1r_gemm(const float* __restrict__ y,
                                                   const float* __restrict__ SR)
{
    extern __shared__ char smem[];
    __nv_bfloat16* sYh = (__nv_bfloat16*)(smem + R_YH);
    __nv_bfloat16* sYl = (__nv_bfloat16*)(smem + R_YL);
    __nv_bfloat16* sSh = (__nv_bfloat16*)(smem + R_SH);
    __nv_bfloat16* sSl = (__nv_bfloat16*)(smem + R_SL);

    const int b0 = blockIdx.x * 128;
    const int x0 = blockIdx.y * 128;
    const int t  = threadIdx.x;
    const int wid = t >> 5;
    const int wm = wid & 1;
    const int wn = wid >> 1;

    #pragma unroll
    for (int i = 0; i < 8; i++) {
        int u = t + i * 256;
        int row = u >> 4;
        int col = (u & 15) * 4;
        float4 v = *(const float4*)&y[(size_t)(b0 + row) * Ydim + col];
        __nv_bfloat16 h0, h1, h2, h3, l0, l1, l2, l3;
        bsplit(v.x, h0, l0); bsplit(v.y, h1, l1); bsplit(v.z, h2, l2); bsplit(v.w, h3, l3);
        *(ushort4*)&sYh[row * RLDA + col] = make_ushort4(__bfloat16_as_ushort(h0), __bfloat16_as_ushort(h1),
                                                         __bfloat16_as_ushort(h2), __bfloat16_as_ushort(h3));
        *(ushort4*)&sYl[row * RLDA + col] = make_ushort4(__bfloat16_as_ushort(l0), __bfloat16_as_ushort(l1),
                                                         __bfloat16_as_ushort(l2), __bfloat16_as_ushort(l3));
    }
    #pragma unroll
    for (int i = 0; i < 8; i++) {
        int u = t + i * 256;
        int row = u >> 5;
        int col = (u & 31) * 4;
        int x = x0 + col;
        float4 v = make_float4(0.f, 0.f, 0.f, 0.f);
        if (x < Xdim) v = *(const float4*)&SR[(size_t)row * Xdim + x];
        __nv_bfloat16 h0, h1, h2, h3, l0, l1, l2, l3;
        bsplit(v.x, h0, l0); bsplit(v.y, h1, l1); bsplit(v.z, h2, l2); bsplit(v.w, h3, l3);
        *(ushort4*)&sSh[row * RLDB + col] = make_ushort4(__bfloat16_as_ushort(h0), __bfloat16_as_ushort(h1),
                                                         __bfloat16_as_ushort(h2), __bfloat16_as_ushort(h3));
        *(ushort4*)&sSl[row * RLDB + col] = make_ushort4(__bfloat16_as_ushort(l0), __bfloat16_as_ushort(l1),
                                                         __bfloat16_as_ushort(l2), __bfloat16_as_ushort(l3));
    }
    __syncthreads();

    wmma::fragment<wmma::accumulator, 16, 16, 16, float> acc[4][2];
    #pragma unroll
    for (int mi = 0; mi < 4; mi++)
        #pragma unroll
        for (int ni = 0; ni < 2; ni++)
            wmma::fill_fragment(acc[mi][ni], 0.f);

    #pragma unroll
    for (int kk = 0; kk < Ydim; kk += 16) {
        wmma::fragment<wmma::matrix_b, 16, 16, 16, __nv_bfloat16, wmma::row_major> fbh[2], fbl[2];
        #pragma unroll
        for (int ni = 0; ni < 2; ni++) {
            wmma::load_matrix_sync(fbh[ni], sSh + kk * RLDB + wn * 32 + ni * 16, RLDB);
            wmma::load_matrix_sync(fbl[ni], sSl + kk * RLDB + wn * 32 + ni * 16, RLDB);
        }
        #pragma unroll
        for (int mi = 0; mi < 4; mi++) {
            wmma::fragment<wmma::matrix_a, 16, 16, 16, __nv_bfloat16, wmma::row_major> fah, fal;
            wmma::load_matrix_sync(fah, sYh + (wm * 64 + mi * 16) * RLDA + kk, RLDA);
            wmma::load_matrix_sync(fal, sYl + (wm * 64 + mi * 16) * RLDA + kk, RLDA);
            #pragma unroll
            for (int ni = 0; ni < 2; ni++) {
                wmma::mma_sync(acc[mi][ni], fah, fbh[ni], acc[mi][ni]);
                wmma::mma_sync(acc[mi][ni], fah, fbl[ni], acc[mi][ni]);
                wmma::mma_sync(acc[mi][ni], fal, fbh[ni], acc[mi][ni]);
            }
        }
    }
    #pragma unroll
    for (int mi = 0; mi < 4; mi++)
        #pragma unroll
        for (int ni = 0; ni < 2; ni++)
            wmma::store_matrix_sync(
                &g_R[(size_t)(b0 + wm * 64 + mi * 16) * Xpad + x0 + wn * 32 + ni * 16],
                acc[mi][ni], Xpad, wmma::mem_row_major);
}

// ============================================================================
// Launch 2: ksplitW — W_g2 -> bf16 hi/lo; tail: Wmu/Wvar^T
// ============================================================================
#define WBLKS (Xpad * Zdim / 4 / 256)
__global__ __launch_bounds__(256) void ksplitW(const float* __restrict__ W,
                                               const float* __restrict__ Wmu,
                                               const float* __restrict__ Wvar) {
    if (blockIdx.x >= WBLKS) {
        int j = blockIdx.x - WBLKS, t = threadIdx.x;
        g_WmuT[j * Zdim + t]  = Wmu[t * Ydim + j];
        g_WvarT[j * Zdim + t] = Wvar[t * Ydim + j];
        return;
    }
    int u = blockIdx.x * 256 + threadIdx.x;
    int x = u >> 6;
    int kg = (u & 63) * 4;
    float4 v = make_float4(0.f, 0.f, 0.f, 0.f);
    if (x < Xdim) v = *(const float4*)&W[(size_t)x * Zdim + kg];
    __nv_bfloat16 h0, h1, h2, h3, l0, l1, l2, l3;
    bsplit(v.x, h0, l0); bsplit(v.y, h1, l1); bsplit(v.z, h2, l2); bsplit(v.w, h3, l3);
    *(ushort4*)&g_Wh[(size_t)u * 4] = make_ushort4(__bfloat16_as_ushort(h0), __bfloat16_as_ushort(h1),
                                                   __bfloat16_as_ushort(h2), __bfloat16_as_ushort(h3));
    *(ushort4*)&g_Wl[(size_t)u * 4] = make_ushort4(__bfloat16_as_ushort(l0), __bfloat16_as_ushort(l1),
                                                   __bfloat16_as_ushort(l2), __bfloat16_as_ushort(l3));
}

// ============================================================================
// Launch 3: K0 — 8 batch rows per block; coalesced [Y,Z] weight streams.
// ============================================================================
__global__ __launch_bounds__(256) void k0_small(
    const float* __restrict__ z, const float* __restrict__ y,
    const float* __restrict__ bmu, const float* __restrict__ bvar,
    const float* __restrict__ styleL,
    float* __restrict__ out_mu, float* __restrict__ out_var)
{
    __shared__ float ys[8][Ydim];
    __shared__ float stl[8][Zdim];
    const int b0 = blockIdx.x * 8;
    const int t  = threadIdx.x;

    #pragma unroll
    for (int i = 0; i < 2; i++) {
        int u = t + i * 256;
        ys[u >> 6][u & 63] = y[b0 * Ydim + u];
    }
    __syncthreads();

    float bm = bmu[t], bv = bvar[t];
    float mu[8] = {}, va[8] = {}, tl[8] = {};
    #pragma unroll 4
    for (int j = 0; j < Ydim; j++) {
        float wm = g_WmuT[j * Zdim + t];
        float wv = g_WvarT[j * Zdim + t];
        float sl = styleL[j * Zdim + t];
        #pragma unroll
        for (int r = 0; r < 8; r++) {
            float yj = ys[r][j];
            mu[r] = fmaf(yj, wm, mu[r]);
            va[r] = fmaf(yj, wv, va[r]);
            tl[r] = fmaf(yj, sl, tl[r]);
        }
    }
    #pragma unroll
    for (int r = 0; r < 8; r++) {
        out_mu[(b0 + r) * Zdim + t] = mu[r] + bm;
        float xv = va[r] + bv;
        out_var[(b0 + r) * Zdim + t] = fmaxf(xv, 0.f) + log1pf(__expf(-fabsf(xv)));
        stl[r][t] = tl[r];
    }
    __syncthreads();

    const int w = t >> 5, l = t & 31;
    const float* zr = z + (size_t)(b0 + w) * Zdim;
    float zv[8];
    float m = -1e30f;
    #pragma unroll
    for (int k = 0; k < 8; k++) { zv[k] = zr[l + 32 * k]; m = fmaxf(m, zv[k]); }
    #pragma unroll
    for (int o = 16; o; o >>= 1) m = fmaxf(m, __shfl_xor_sync(0xFFFFFFFFu, m, o));
    float s = 0.f;
    #pragma unroll
    for (int k = 0; k < 8; k++) { zv[k] = __expf(zv[k] - m); s += zv[k]; }
    #pragma unroll
    for (int o = 16; o; o >>= 1) s += __shfl_xor_sync(0xFFFFFFFFu, s, o);
    float inv = 1.f / s;
    #pragma unroll
    for (int k = 0; k < 8; k++) {
        float a = zv[k] * inv * stl[w][l + 32 * k];
        __nv_bfloat16 ah, al;
        bsplit(a, ah, al);
        int idx = (b0 + w) * Zdim + l + 32 * k;
        g_Ah[idx] = ah;
        g_Al[idx] = al;
    }
}

// ============================================================================
// Launch 4: K1C — C = A @ W_g2^T (bf16x3), R7 mainloop (pass-outer MMA order).
//   Epilogue: h = C * R(g_R) -> outx ; smem-reduced BN partials -> g_ps/g_pq.
// ============================================================================
#define LDA 56
#define OFF_AL 14336
#define OFF_WH 28672
#define OFF_WL 43008
#define BUF_STRIDE 57344
#define K1_SMEM (2 * BUF_STRIDE)
#define SC_LD 132
#define SS_OFF 67584
#define SQ_OFF (67584 + 4096)

__global__ __launch_bounds__(256, 2) void k1_gemm(float* __restrict__ outx)
{
    extern __shared__ char smem[];
    const int bt = blockIdx.x;
    const int b0 = bt * 128;
    const int x0 = blockIdx.y * 128;
    const int t  = threadIdx.x;
    const int wid = t >> 5;
    const int wm = wid & 1;
    const int wn = wid >> 1;

    wmma::fragment<wmma::accumulator, 16, 16, 16, float> accC[4][2];
    #pragma unroll
    for (int mi = 0; mi < 4; mi++)
        #pragma unroll
        for (int ni = 0; ni < 2; ni++)
            wmma::fill_fragment(accC[mi][ni], 0.f);

    const uint32_t sbase = smem_u32(smem);

    auto stage = [&](int c, int p) {
        const int kc = c * 32;
        const uint32_t bb = sbase + p * BUF_STRIDE;
        #pragma unroll
        for (int i = 0; i < 2; i++) {
            int u = t + i * 256;
            int row = u >> 2;
            int cg = (u & 3) * 8;
            uint32_t so = (row * LDA + cg) * 2;
            CP_ASYNC16(bb + so,           &g_Ah[(size_t)(b0 + row) * Zdim + kc + cg]);
            CP_ASYNC16(bb + OFF_AL + so,  &g_Al[(size_t)(b0 + row) * Zdim + kc + cg]);
            CP_ASYNC16(bb + OFF_WH + so,  &g_Wh[(size_t)(x0 + row) * Zdim + kc + cg]);
            CP_ASYNC16(bb + OFF_WL + so,  &g_Wl[(size_t)(x0 + row) * Zdim + kc + cg]);
        }
        CP_COMMIT();
    };

    stage(0, 0);
    for (int c = 0; c < 8; c++) {
        if (c < 7) { stage(c + 1, (c + 1) & 1); CP_WAIT1(); }
        else       { CP_WAIT0(); }
        __syncthreads();

        char* buf = smem + (c & 1) * BUF_STRIDE;
        __nv_bfloat16* sAh = (__nv_bfloat16*)buf;
        __nv_bfloat16* sAl = (__nv_bfloat16*)(buf + OFF_AL);
        __nv_bfloat16* sWh = (__nv_bfloat16*)(buf + OFF_WH);
        __nv_bfloat16* sWl = (__nv_bfloat16*)(buf + OFF_WL);

        #pragma unroll
        for (int k2 = 0; k2 < 32; k2 += 16) {
            wmma::fragment<wmma::matrix_b, 16, 16, 16, __nv_bfloat16, wmma::col_major> fbh[2], fbl[2];
            #pragma unroll
            for (int ni = 0; ni < 2; ni++) {
                wmma::load_matrix_sync(fbh[ni], sWh + (wn * 32 + ni * 16) * LDA + k2, LDA);
                wmma::load_matrix_sync(fbl[ni], sWl + (wn * 32 + ni * 16) * LDA + k2, LDA);
            }
            #pragma unroll
            for (int mi = 0; mi < 4; mi++) {
                wmma::fragment<wmma::matrix_a, 16, 16, 16, __nv_bfloat16, wmma::row_major> fah, fal;
                wmma::load_matrix_sync(fah, sAh + (wm * 64 + mi * 16) * LDA + k2, LDA);
                wmma::load_matrix_sync(fal, sAl + (wm * 64 + mi * 16) * LDA + k2, LDA);
                // pass-outer / ni-inner: dependent acc reuses are 2 ops apart
                #pragma unroll
                for (int ni = 0; ni < 2; ni++)
                    wmma::mma_sync(accC[mi][ni], fah, fbh[ni], accC[mi][ni]);
                #pragma unroll
                for (int ni = 0; ni < 2; ni++)
                    wmma::mma_sync(accC[mi][ni], fah, fbl[ni], accC[mi][ni]);
                #pragma unroll
                for (int ni = 0; ni < 2; ni++)
                    wmma::mma_sync(accC[mi][ni], fal, fbh[ni], accC[mi][ni]);
            }
        }
        __syncthreads();
    }

    // ---------------- epilogue: C -> smem, h = C*R -> outx, BN partials -----
    float* sC = (float*)smem;
    float* sS = (float*)(smem + SS_OFF);
    float* sQ = (float*)(smem + SQ_OFF);
    #pragma unroll
    for (int mi = 0; mi < 4; mi++)
        #pragma unroll
        for (int ni = 0; ni < 2; ni++)
            wmma::store_matrix_sync(&sC[(wm * 64 + mi * 16) * SC_LD + wn * 32 + ni * 16],
                                    accC[mi][ni], SC_LD, wmma::mem_row_major);
    __syncthreads();

    {
        const int lc = (t & 31) * 4;
        const int r0 = t >> 5;
        const int x  = x0 + lc;
        float s0 = 0.f, s1 = 0.f, s2 = 0.f, s3 = 0.f;
        float q0 = 0.f, q1 = 0.f, q2 = 0.f, q3 = 0.f;
        if (x < Xdim) {
            #pragma unroll
            for (int i = 0; i < 16; i++) {
                int row = r0 + i * 8;
                float4 cv = *(float4*)&sC[row * SC_LD + lc];
                float4 rv = *(const float4*)&g_R[(size_t)(b0 + row) * Xpad + x];
                cv.x *= rv.x; cv.y *= rv.y; cv.z *= rv.z; cv.w *= rv.w;
                *(float4*)&outx[(size_t)(b0 + row) * Xdim + x] = cv;
                s0 += cv.x; q0 = fmaf(cv.x, cv.x, q0);
                s1 += cv.y; q1 = fmaf(cv.y, cv.y, q1);
                s2 += cv.z; q2 = fmaf(cv.z, cv.z, q2);
                s3 += cv.w; q3 = fmaf(cv.w, cv.w, q3);
            }
        }
        *(float4*)&sS[r0 * 128 + lc] = make_float4(s0, s1, s2, s3);
        *(float4*)&sQ[r0 * 128 + lc] = make_float4(q0, q1, q2, q3);
    }
    __syncthreads();

    if (t < 32) {
        const int lc = t * 4;
        const int x  = x0 + lc;
        if (x < Xdim) {
            float4 S = make_float4(0.f, 0.f, 0.f, 0.f);
            float4 Q = make_float4(0.f, 0.f, 0.f, 0.f);
            #pragma unroll
            for (int r = 0; r < 8; r++) {
                float4 a = *(float4*)&sS[r * 128 + lc];
                float4 b = *(float4*)&sQ[r * 128 + lc];
                S.x += a.x; S.y += a.y; S.z += a.z; S.w += a.w;
                Q.x += b.x; Q.y += b.y; Q.z += b.z; Q.w += b.w;
            }
            *(float4*)&g_ps[(size_t)bt * Xpad + x] = S;
            *(float4*)&g_pq[(size_t)bt * Xpad + x] = Q;
        }
    }
}

// ============================================================================
// Launch 5: kstats_final — reduce 32 partials -> BN scale/shift
// ============================================================================
__global__ __launch_bounds__(256) void kstats_final(
    const float* __restrict__ gamma, const float* __restrict__ beta)
{
    int x = blockIdx.x * 256 + threadIdx.x;
    if (x >= Xdim) return;
    float s = 0.f, q = 0.f;
    #pragma unroll
    for (int j = 0; j < NBT; j++) {
        s += g_ps[(size_t)j * Xpad + x];
        q += g_pq[(size_t)j * Xpad + x];
    }
    const float invB = 1.f / (float)Bdim;
    float mean = s * invB;
    float var  = q * invB - mean * mean;
    float inv  = rsqrtf(var + BN_EPS);
    float sc   = inv * gamma[x];
    g_scale[x] = sc;
    g_shift[x] = beta[x] - mean * sc;
}

// ============================================================================
// Launch 6: K3 — affine + softmax, 3-phase, ONE exp per element.
//   P1: a = h*scale+shift -> smem, track max (no exp)
//   P2: e = exp(a - M) -> smem (overwrite), sum
//   P3: out = e * (1/S)
// ============================================================================
#define K3_SMEM (Xdim * 4)

__global__ __launch_bounds__(512) void k3_softmax(float* __restrict__ outx)
{
    extern __shared__ float sa[];
    const int b = blockIdx.x;
    const int t = threadIdx.x;
    float4* row = (float4*)(outx + (size_t)b * Xdim);
    const float4* sc4 = (const float4*)g_scale;
    const float4* sh4 = (const float4*)g_shift;
    const int N4 = Xdim / 4;

    __shared__ float sred[16];
    const int w = t >> 5, l = t & 31;

    // ---- phase 1: affine -> smem, max only ----
    float m = -1e30f;
    for (int i = t; i < N4; i += 512) {
        float4 v = row[i], sc = sc4[i], sh = sh4[i];
        float4 a;
        a.x = fmaf(v.x, sc.x, sh.x);
        a.y = fmaf(v.y, sc.y, sh.y);
        a.z = fmaf(v.z, sc.z, sh.z);
        a.w = fmaf(v.w, sc.w, sh.w);
        *(float4*)&sa[i * 4] = a;
        m = fmaxf(m, fmaxf(fmaxf(a.x, a.y), fmaxf(a.z, a.w)));
    }
    #pragma unroll
    for (int o = 16; o; o >>= 1) m = fmaxf(m, __shfl_xor_sync(0xFFFFFFFFu, m, o));
    if (l == 0) sred[w] = m;
    __syncthreads();
    if (w == 0) {
        m = (l < 16) ? sred[l] : -1e30f;
        #pragma unroll
        for (int o = 8; o; o >>= 1) m = fmaxf(m, __shfl_xor_sync(0xFFFFFFFFu, m, o));
        if (l == 0) sred[0] = m;
    }
    __syncthreads();
    const float M = sred[0];
    __syncthreads();

    // ---- phase 2: exp once -> smem, sum ----
    float s = 0.f;
    for (int i = t; i < N4; i += 512) {
        float4 a = *(float4*)&sa[i * 4];
        float4 e;
        e.x = __expf(a.x - M);
        e.y = __expf(a.y - M);
        e.z = __expf(a.z - M);
        e.w = __expf(a.w - M);
        *(float4*)&sa[i * 4] = e;
        s += (e.x + e.y) + (e.z + e.w);
    }
    #pragma unroll
    for (int o = 16; o; o >>= 1) s += __shfl_xor_sync(0xFFFFFFFFu, s, o);
    if (l == 0) sred[w] = s;
    __syncthreads();
    if (w == 0) {
        s = (l < 16) ? sred[l] : 0.f;
        #pragma unroll
        for (int o = 8; o; o >>= 1) s += __shfl_xor_sync(0xFFFFFFFFu, s, o);
        if (l == 0) sred[0] = s;
    }
    __syncthreads();
    const float invS = 1.f / sred[0];

    // ---- phase 3: scale + write out ----
    for (int i = t; i < N4; i += 512) {
        float4 e = *(float4*)&sa[i * 4];
        e.x *= invS; e.y *= invS; e.z *= invS; e.w *= invS;
        row[i] = e;
    }
}

// ============================================================================
extern "C" void kernel_launch(void* const* d_in, const int* in_sizes, int n_in,
                              void* d_out, int out_size)
{
    const float* z      = (const float*)d_in[0];
    const float* y      = (const float*)d_in[1];
    const float* Wmu    = (const float*)d_in[2];
    const float* bmu    = (const float*)d_in[3];
    const float* Wvar   = (const float*)d_in[4];
    const float* bvar   = (const float*)d_in[5];
    const float* Wg2    = (const float*)d_in[6];
    const float* styleL = (const float*)d_in[7];
    const float* styleR = (const float*)d_in[8];
    const float* gamma  = (const float*)d_in[9];
    const float* beta   = (const float*)d_in[10];

    float* out     = (float*)d_out;
    float* out_mu  = out;
    float* out_var = out + (size_t)Bdim * Zdim;
    float* outx    = out + (size_t)2 * Bdim * Zdim;

    cudaFuncSetAttribute(k1r_gemm, cudaFuncAttributeMaxDynamicSharedMemorySize, KR_SMEM);
    cudaFuncSetAttribute(k1_gemm, cudaFuncAttributeMaxDynamicSharedMemorySize, K1_SMEM);
    cudaFuncSetAttribute(k3_softmax, cudaFuncAttributeMaxDynamicSharedMemorySize, K3_SMEM);

    dim3 g1(Bdim / 128, Xpad / 128);
    k1r_gemm<<<g1, 256, KR_SMEM>>>(y, styleR);               // 1
    ksplitW<<<WBLKS + Ydim, 256>>>(Wg2, Wmu, Wvar);          // 2
    k0_small<<<Bdim / 8, 256>>>(z, y, bmu, bvar, styleL, out_mu, out_var);  // 3
    k1_gemm<<<g1, 256, K1_SMEM>>>(outx);                     // 4  <- ncu profiles this

    kstats_final<<<(Xdim + 255) / 256, 256>>>(gamma, beta);  // 5
    k3_softmax<<<Bdim, 512, K3_SMEM>>>(outx);                // 6
}

// round 14
// speedup vs baseline: 1.0195x; 1.0195x over previous
#include <cuda_runtime.h>
#include <cuda_bf16.h>
#include <mma.h>
#include <math.h>
#include <stdint.h>

using namespace nvcuda;

#define Bdim 4096
#define Zdim 256
#define Ydim 64
#define Xdim 30000
#define Xpad 30080
#define NBT  32            // number of b-tiles (Bdim/128)
#define BN_EPS 1e-3f

// ---------------- device scratch ----------------
__device__ __nv_bfloat16 g_Ah[Bdim * Zdim], g_Al[Bdim * Zdim];   // zs*tmp_L
__device__ __nv_bfloat16 g_Wh[Xpad * Zdim], g_Wl[Xpad * Zdim];   // W_g2 (padded X)
__device__ float g_R[(size_t)Bdim * Xpad];                       // R = y @ style_R
__device__ float g_WmuT[Ydim * Zdim], g_WvarT[Ydim * Zdim];      // transposed [Y,Z]
__device__ float g_ps[NBT * Xpad], g_pq[NBT * Xpad];             // BN partial sums
__device__ float g_scale[Xdim], g_shift[Xdim];

__device__ __forceinline__ void bsplit(float v, __nv_bfloat16& h, __nv_bfloat16& l) {
    h = __float2bfloat16(v);
    l = __float2bfloat16(v - __bfloat162float(h));
}

__device__ __forceinline__ uint32_t smem_u32(const void* p) {
    uint32_t a;
    asm("{ .reg .u64 t; cvta.to.shared.u64 t, %1; cvt.u32.u64 %0, t; }" : "=r"(a) : "l"(p));
    return a;
}
#define CP_ASYNC16(dst, src) \
    asm volatile("cp.async.cg.shared.global [%0], [%1], 16;" :: "r"(dst), "l"(src))
#define CP_COMMIT() asm volatile("cp.async.commit_group;")
#define CP_WAIT1()  asm volatile("cp.async.wait_group 1;")
#define CP_WAIT0()  asm volatile("cp.async.wait_group 0;")

// ============================================================================
// Launch 1: k1R — R = y @ style_R (bf16x3), self-converting, -> g_R
// ============================================================================
#define RLDA 72
#define RLDB 136
#define R_YH 0
#define R_YL 18432
#define R_SH 36864
#define R_SL 54272
#define KR_SMEM 71680

__global__ __launch_bounds__(256, 2) void k1r_gemm(const float* __restrict__ y,
                                                   const float* __restrict__ SR)
{
    extern __shared__ char smem[];
    __nv_bfloat16* sYh = (__nv_bfloat16*)(smem + R_YH);
    __nv_bfloat16* sYl = (__nv_bfloat16*)(smem + R_YL);
    __nv_bfloat16* sSh = (__nv_bfloat16*)(smem + R_SH);
    __nv_bfloat16* sSl = (__nv_bfloat16*)(smem + R_SL);

    const int b0 = blockIdx.x * 128;
    const int x0 = blockIdx.y * 128;
    const int t  = threadIdx.x;
    const int wid = t >> 5;
    const int wm = wid & 1;
    const int wn = wid >> 1;

    #pragma unroll
    for (int i = 0; i < 8; i++) {
        int u = t + i * 256;
        int row = u >> 4;
        int col = (u & 15) * 4;
        float4 v = *(const float4*)&y[(size_t)(b0 + row) * Ydim + col];
        __nv_bfloat16 h0, h1, h2, h3, l0, l1, l2, l3;
        bsplit(v.x, h0, l0); bsplit(v.y, h1, l1); bsplit(v.z, h2, l2); bsplit(v.w, h3, l3);
        *(ushort4*)&sYh[row * RLDA + col] = make_ushort4(__bfloat16_as_ushort(h0), __bfloat16_as_ushort(h1),
                                                         __bfloat16_as_ushort(h2), __bfloat16_as_ushort(h3));
        *(ushort4*)&sYl[row * RLDA + col] = make_ushort4(__bfloat16_as_ushort(l0), __bfloat16_as_ushort(l1),
                                                         __bfloat16_as_ushort(l2), __bfloat16_as_ushort(l3));
    }
    #pragma unroll
    for (int i = 0; i < 8; i++) {
        int u = t + i * 256;
        int row = u >> 5;
        int col = (u & 31) * 4;
        int x = x0 + col;
        float4 v = make_float4(0.f, 0.f, 0.f, 0.f);
        if (x < Xdim) v = *(const float4*)&SR[(size_t)row * Xdim + x];
        __nv_bfloat16 h0, h1, h2, h3, l0, l1, l2, l3;
        bsplit(v.x, h0, l0); bsplit(v.y, h1, l1); bsplit(v.z, h2, l2); bsplit(v.w, h3, l3);
        *(ushort4*)&sSh[row * RLDB + col] = make_ushort4(__bfloat16_as_ushort(h0), __bfloat16_as_ushort(h1),
                                                         __bfloat16_as_ushort(h2), __bfloat16_as_ushort(h3));
        *(ushort4*)&sSl[row * RLDB + col] = make_ushort4(__bfloat16_as_ushort(l0), __bfloat16_as_ushort(l1),
                                                         __bfloat16_as_ushort(l2), __bfloat16_as_ushort(l3));
    }
    __syncthreads();

    wmma::fragment<wmma::accumulator, 16, 16, 16, float> acc[4][2];
    #pragma unroll
    for (int mi = 0; mi < 4; mi++)
        #pragma unroll
        for (int ni = 0; ni < 2; ni++)
            wmma::fill_fragment(acc[mi][ni], 0.f);

    #pragma unroll
    for (int kk = 0; kk < Ydim; kk += 16) {
        wmma::fragment<wmma::matrix_b, 16, 16, 16, __nv_bfloat16, wmma::row_major> fbh[2], fbl[2];
        #pragma unroll
        for (int ni = 0; ni < 2; ni++) {
            wmma::load_matrix_sync(fbh[ni], sSh + kk * RLDB + wn * 32 + ni * 16, RLDB);
            wmma::load_matrix_sync(fbl[ni], sSl + kk * RLDB + wn * 32 + ni * 16, RLDB);
        }
        #pragma unroll
        for (int mi = 0; mi < 4; mi++) {
            wmma::fragment<wmma::matrix_a, 16, 16, 16, __nv_bfloat16, wmma::row_major> fah, fal;
            wmma::load_matrix_sync(fah, sYh + (wm * 64 + mi * 16) * RLDA + kk, RLDA);
            wmma::load_matrix_sync(fal, sYl + (wm * 64 + mi * 16) * RLDA + kk, RLDA);
            #pragma unroll
            for (int ni = 0; ni < 2; ni++) {
                wmma::mma_sync(acc[mi][ni], fah, fbh[ni], acc[mi][ni]);
                wmma::mma_sync(acc[mi][ni], fah, fbl[ni], acc[mi][ni]);
                wmma::mma_sync(acc[mi][ni], fal, fbh[ni], acc[mi][ni]);
            }
        }
    }
    #pragma unroll
    for (int mi = 0; mi < 4; mi++)
        #pragma unroll
        for (int ni = 0; ni < 2; ni++)
            wmma::store_matrix_sync(
                &g_R[(size_t)(b0 + wm * 64 + mi * 16) * Xpad + x0 + wn * 32 + ni * 16],
                acc[mi][ni], Xpad, wmma::mem_row_major);
}

// ============================================================================
// Launch 2: ksplitW — W_g2 -> bf16 hi/lo; tail: Wmu/Wvar^T
// ============================================================================
#define WBLKS (Xpad * Zdim / 4 / 256)
__global__ __launch_bounds__(256) void ksplitW(const float* __restrict__ W,
                                               const float* __restrict__ Wmu,
                                               const float* __restrict__ Wvar) {
    if (blockIdx.x >= WBLKS) {
        int j = blockIdx.x - WBLKS, t = threadIdx.x;
        g_WmuT[j * Zdim + t]  = Wmu[t * Ydim + j];
        g_WvarT[j * Zdim + t] = Wvar[t * Ydim + j];
        return;
    }
    int u = blockIdx.x * 256 + threadIdx.x;
    int x = u >> 6;
    int kg = (u & 63) * 4;
    float4 v = make_float4(0.f, 0.f, 0.f, 0.f);
    if (x < Xdim) v = *(const float4*)&W[(size_t)x * Zdim + kg];
    __nv_bfloat16 h0, h1, h2, h3, l0, l1, l2, l3;
    bsplit(v.x, h0, l0); bsplit(v.y, h1, l1); bsplit(v.z, h2, l2); bsplit(v.w, h3, l3);
    *(ushort4*)&g_Wh[(size_t)u * 4] = make_ushort4(__bfloat16_as_ushort(h0), __bfloat16_as_ushort(h1),
                                                   __bfloat16_as_ushort(h2), __bfloat16_as_ushort(h3));
    *(ushort4*)&g_Wl[(size_t)u * 4] = make_ushort4(__bfloat16_as_ushort(l0), __bfloat16_as_ushort(l1),
                                                   __bfloat16_as_ushort(l2), __bfloat16_as_ushort(l3));
}

// ============================================================================
// Launch 3: K0 — 8 batch rows per block; coalesced [Y,Z] weight streams.
// ============================================================================
__global__ __launch_bounds__(256) void k0_small(
    const float* __restrict__ z, const float* __restrict__ y,
    const float* __restrict__ bmu, const float* __restrict__ bvar,
    const float* __restrict__ styleL,
    float* __restrict__ out_mu, float* __restrict__ out_var)
{
    __shared__ float ys[8][Ydim];
    __shared__ float stl[8][Zdim];
    const int b0 = blockIdx.x * 8;
    const int t  = threadIdx.x;

    #pragma unroll
    for (int i = 0; i < 2; i++) {
        int u = t + i * 256;
        ys[u >> 6][u & 63] = y[b0 * Ydim + u];
    }
    __syncthreads();

    float bm = bmu[t], bv = bvar[t];
    float mu[8] = {}, va[8] = {}, tl[8] = {};
    #pragma unroll 4
    for (int j = 0; j < Ydim; j++) {
        float wm = g_WmuT[j * Zdim + t];
        float wv = g_WvarT[j * Zdim + t];
        float sl = styleL[j * Zdim + t];
        #pragma unroll
        for (int r = 0; r < 8; r++) {
            float yj = ys[r][j];
            mu[r] = fmaf(yj, wm, mu[r]);
            va[r] = fmaf(yj, wv, va[r]);
            tl[r] = fmaf(yj, sl, tl[r]);
        }
    }
    #pragma unroll
    for (int r = 0; r < 8; r++) {
        out_mu[(b0 + r) * Zdim + t] = mu[r] + bm;
        float xv = va[r] + bv;
        out_var[(b0 + r) * Zdim + t] = fmaxf(xv, 0.f) + log1pf(__expf(-fabsf(xv)));
        stl[r][t] = tl[r];
    }
    __syncthreads();

    const int w = t >> 5, l = t & 31;
    const float* zr = z + (size_t)(b0 + w) * Zdim;
    float zv[8];
    float m = -1e30f;
    #pragma unroll
    for (int k = 0; k < 8; k++) { zv[k] = zr[l + 32 * k]; m = fmaxf(m, zv[k]); }
    #pragma unroll
    for (int o = 16; o; o >>= 1) m = fmaxf(m, __shfl_xor_sync(0xFFFFFFFFu, m, o));
    float s = 0.f;
    #pragma unroll
    for (int k = 0; k < 8; k++) { zv[k] = __expf(zv[k] - m); s += zv[k]; }
    #pragma unroll
    for (int o = 16; o; o >>= 1) s += __shfl_xor_sync(0xFFFFFFFFu, s, o);
    float inv = 1.f / s;
    #pragma unroll
    for (int k = 0; k < 8; k++) {
        float a = zv[k] * inv * stl[w][l + 32 * k];
        __nv_bfloat16 ah, al;
        bsplit(a, ah, al);
        int idx = (b0 + w) * Zdim + l + 32 * k;
        g_Ah[idx] = ah;
        g_Al[idx] = al;
    }
}

// ============================================================================
// Launch 4: K1C — C = A @ W_g2^T (bf16x3), R7 mainloop (pass-outer MMA order).
//   Epilogue: h = C * R(g_R) -> outx ; smem-reduced BN partials -> g_ps/g_pq.
// ============================================================================
#define LDA 56
#define OFF_AL 14336
#define OFF_WH 28672
#define OFF_WL 43008
#define BUF_STRIDE 57344
#define K1_SMEM (2 * BUF_STRIDE)
#define SC_LD 132
#define SS_OFF 67584
#define SQ_OFF (67584 + 4096)

__global__ __launch_bounds__(256, 2) void k1_gemm(float* __restrict__ outx)
{
    extern __shared__ char smem[];
    const int bt = blockIdx.x;
    const int b0 = bt * 128;
    const int x0 = blockIdx.y * 128;
    const int t  = threadIdx.x;
    const int wid = t >> 5;
    const int wm = wid & 1;
    const int wn = wid >> 1;

    wmma::fragment<wmma::accumulator, 16, 16, 16, float> accC[4][2];
    #pragma unroll
    for (int mi = 0; mi < 4; mi++)
        #pragma unroll
        for (int ni = 0; ni < 2; ni++)
            wmma::fill_fragment(accC[mi][ni], 0.f);

    const uint32_t sbase = smem_u32(smem);

    auto stage = [&](int c, int p) {
        const int kc = c * 32;
        const uint32_t bb = sbase + p * BUF_STRIDE;
        #pragma unroll
        for (int i = 0; i < 2; i++) {
            int u = t + i * 256;
            int row = u >> 2;
            int cg = (u & 3) * 8;
            uint32_t so = (row * LDA + cg) * 2;
            CP_ASYNC16(bb + so,           &g_Ah[(size_t)(b0 + row) * Zdim + kc + cg]);
            CP_ASYNC16(bb + OFF_AL + so,  &g_Al[(size_t)(b0 + row) * Zdim + kc + cg]);
            CP_ASYNC16(bb + OFF_WH + so,  &g_Wh[(size_t)(x0 + row) * Zdim + kc + cg]);
            CP_ASYNC16(bb + OFF_WL + so,  &g_Wl[(size_t)(x0 + row) * Zdim + kc + cg]);
        }
        CP_COMMIT();
    };

    stage(0, 0);
    for (int c = 0; c < 8; c++) {
        if (c < 7) { stage(c + 1, (c + 1) & 1); CP_WAIT1(); }
        else       { CP_WAIT0(); }
        __syncthreads();

        char* buf = smem + (c & 1) * BUF_STRIDE;
        __nv_bfloat16* sAh = (__nv_bfloat16*)buf;
        __nv_bfloat16* sAl = (__nv_bfloat16*)(buf + OFF_AL);
        __nv_bfloat16* sWh = (__nv_bfloat16*)(buf + OFF_WH);
        __nv_bfloat16* sWl = (__nv_bfloat16*)(buf + OFF_WL);

        #pragma unroll
        for (int k2 = 0; k2 < 32; k2 += 16) {
            wmma::fragment<wmma::matrix_b, 16, 16, 16, __nv_bfloat16, wmma::col_major> fbh[2], fbl[2];
            #pragma unroll
            for (int ni = 0; ni < 2; ni++) {
                wmma::load_matrix_sync(fbh[ni], sWh + (wn * 32 + ni * 16) * LDA + k2, LDA);
                wmma::load_matrix_sync(fbl[ni], sWl + (wn * 32 + ni * 16) * LDA + k2, LDA);
            }
            #pragma unroll
            for (int mi = 0; mi < 4; mi++) {
                wmma::fragment<wmma::matrix_a, 16, 16, 16, __nv_bfloat16, wmma::row_major> fah, fal;
                wmma::load_matrix_sync(fah, sAh + (wm * 64 + mi * 16) * LDA + k2, LDA);
                wmma::load_matrix_sync(fal, sAl + (wm * 64 + mi * 16) * LDA + k2, LDA);
                // pass-outer / ni-inner: dependent acc reuses are 2 ops apart
                #pragma unroll
                for (int ni = 0; ni < 2; ni++)
                    wmma::mma_sync(accC[mi][ni], fah, fbh[ni], accC[mi][ni]);
                #pragma unroll
                for (int ni = 0; ni < 2; ni++)
                    wmma::mma_sync(accC[mi][ni], fah, fbl[ni], accC[mi][ni]);
                #pragma unroll
                for (int ni = 0; ni < 2; ni++)
                    wmma::mma_sync(accC[mi][ni], fal, fbh[ni], accC[mi][ni]);
            }
        }
        __syncthreads();
    }

    // ---------------- epilogue: C -> smem, h = C*R -> outx, BN partials -----
    float* sC = (float*)smem;
    float* sS = (float*)(smem + SS_OFF);
    float* sQ = (float*)(smem + SQ_OFF);
    #pragma unroll
    for (int mi = 0; mi < 4; mi++)
        #pragma unroll
        for (int ni = 0; ni < 2; ni++)
            wmma::store_matrix_sync(&sC[(wm * 64 + mi * 16) * SC_LD + wn * 32 + ni * 16],
                                    accC[mi][ni], SC_LD, wmma::mem_row_major);
    __syncthreads();

    {
        const int lc = (t & 31) * 4;
        const int r0 = t >> 5;
        const int x  = x0 + lc;
        float s0 = 0.f, s1 = 0.f, s2 = 0.f, s3 = 0.f;
        float q0 = 0.f, q1 = 0.f, q2 = 0.f, q3 = 0.f;
        if (x < Xdim) {
            #pragma unroll
            for (int i = 0; i < 16; i++) {
                int row = r0 + i * 8;
                float4 cv = *(float4*)&sC[row * SC_LD + lc];
                float4 rv = *(const float4*)&g_R[(size_t)(b0 + row) * Xpad + x];
                cv.x *= rv.x; cv.y *= rv.y; cv.z *= rv.z; cv.w *= rv.w;
                *(float4*)&outx[(size_t)(b0 + row) * Xdim + x] = cv;
                s0 += cv.x; q0 = fmaf(cv.x, cv.x, q0);
                s1 += cv.y; q1 = fmaf(cv.y, cv.y, q1);
                s2 += cv.z; q2 = fmaf(cv.z, cv.z, q2);
                s3 += cv.w; q3 = fmaf(cv.w, cv.w, q3);
            }
        }
        *(float4*)&sS[r0 * 128 + lc] = make_float4(s0, s1, s2, s3);
        *(float4*)&sQ[r0 * 128 + lc] = make_float4(q0, q1, q2, q3);
    }
    __syncthreads();

    if (t < 32) {
        const int lc = t * 4;
        const int x  = x0 + lc;
        if (x < Xdim) {
            float4 S = make_float4(0.f, 0.f, 0.f, 0.f);
            float4 Q = make_float4(0.f, 0.f, 0.f, 0.f);
            #pragma unroll
            for (int r = 0; r < 8; r++) {
                float4 a = *(float4*)&sS[r * 128 + lc];
                float4 b = *(float4*)&sQ[r * 128 + lc];
                S.x += a.x; S.y += a.y; S.z += a.z; S.w += a.w;
                Q.x += b.x; Q.y += b.y; Q.z += b.z; Q.w += b.w;
            }
            *(float4*)&g_ps[(size_t)bt * Xpad + x] = S;
            *(float4*)&g_pq[(size_t)bt * Xpad + x] = Q;
        }
    }
}

// ============================================================================
// Launch 5: kstats_final — reduce 32 partials -> BN scale/shift
// ============================================================================
__global__ __launch_bounds__(256) void kstats_final(
    const float* __restrict__ gamma, const float* __restrict__ beta)
{
    int x = blockIdx.x * 256 + threadIdx.x;
    if (x >= Xdim) return;
    float s = 0.f, q = 0.f;
    #pragma unroll
    for (int j = 0; j < NBT; j++) {
        s += g_ps[(size_t)j * Xpad + x];
        q += g_pq[(size_t)j * Xpad + x];
    }
    const float invB = 1.f / (float)Bdim;
    float mean = s * invB;
    float var  = q * invB - mean * mean;
    float inv  = rsqrtf(var + BN_EPS);
    float sc   = inv * gamma[x];
    g_scale[x] = sc;
    g_shift[x] = beta[x] - mean * sc;
}

// ============================================================================
// Launch 6: K3 — affine + softmax; online 2-phase, logits cached in smem
//   (R12 version — measured fastest).
// ============================================================================
#define K3_SMEM (Xdim * 4)

__global__ __launch_bounds__(512) void k3_softmax(float* __restrict__ outx)
{
    extern __shared__ float sa[];
    const int b = blockIdx.x;
    const int t = threadIdx.x;
    float4* row = (float4*)(outx + (size_t)b * Xdim);
    const float4* sc4 = (const float4*)g_scale;
    const float4* sh4 = (const float4*)g_shift;
    const int N4 = Xdim / 4;

    float m = -1e30f, s = 0.f;
    for (int i = t; i < N4; i += 512) {
        float4 v = row[i], sc = sc4[i], sh = sh4[i];
        float4 a;
        a.x = fmaf(v.x, sc.x, sh.x);
        a.y = fmaf(v.y, sc.y, sh.y);
        a.z = fmaf(v.z, sc.z, sh.z);
        a.w = fmaf(v.w, sc.w, sh.w);
        *(float4*)&sa[i * 4] = a;
        float mv = fmaxf(fmaxf(a.x, a.y), fmaxf(a.z, a.w));
        float nm = fmaxf(m, mv);
        s = s * __expf(m - nm) + __expf(a.x - nm) + __expf(a.y - nm)
          + __expf(a.z - nm) + __expf(a.w - nm);
        m = nm;
    }
    #pragma unroll
    for (int o = 16; o; o >>= 1) {
        float mo = __shfl_xor_sync(0xFFFFFFFFu, m, o);
        float so = __shfl_xor_sync(0xFFFFFFFFu, s, o);
        float nm = fmaxf(m, mo);
        s = s * __expf(m - nm) + so * __expf(mo - nm);
        m = nm;
    }
    __shared__ float sm[16], ss[16];
    int w = t >> 5, l = t & 31;
    if (l == 0) { sm[w] = m; ss[w] = s; }
    __syncthreads();
    if (w == 0) {
        m = (l < 16) ? sm[l] : -1e30f;
        s = (l < 16) ? ss[l] : 0.f;
        #pragma unroll
        for (int o = 8; o; o >>= 1) {
            float mo = __shfl_xor_sync(0xFFFFFFFFu, m, o);
            float so = __shfl_xor_sync(0xFFFFFFFFu, s, o);
            float nm = fmaxf(m, mo);
            s = s * __expf(m - nm) + so * __expf(mo - nm);
            m = nm;
        }
        if (l == 0) { sm[0] = m; ss[0] = s; }
    }
    __syncthreads();
    const float M = sm[0];
    const float invS = 1.f / ss[0];

    for (int i = t; i < N4; i += 512) {
        float4 a = *(float4*)&sa[i * 4];
        float4 o;
        o.x = __expf(a.x - M) * invS;
        o.y = __expf(a.y - M) * invS;
        o.z = __expf(a.z - M) * invS;
        o.w = __expf(a.w - M) * invS;
        row[i] = o;
    }
}

// ============================================================================
extern "C" void kernel_launch(void* const* d_in, const int* in_sizes, int n_in,
                              void* d_out, int out_size)
{
    const float* z      = (const float*)d_in[0];
    const float* y      = (const float*)d_in[1];
    const float* Wmu    = (const float*)d_in[2];
    const float* bmu    = (const float*)d_in[3];
    const float* Wvar   = (const float*)d_in[4];
    const float* bvar   = (const float*)d_in[5];
    const float* Wg2    = (const float*)d_in[6];
    const float* styleL = (const float*)d_in[7];
    const float* styleR = (const float*)d_in[8];
    const float* gamma  = (const float*)d_in[9];
    const float* beta   = (const float*)d_in[10];

    float* out     = (float*)d_out;
    float* out_mu  = out;
    float* out_var = out + (size_t)Bdim * Zdim;
    float* outx    = out + (size_t)2 * Bdim * Zdim;

    cudaFuncSetAttribute(k1r_gemm, cudaFuncAttributeMaxDynamicSharedMemorySize, KR_SMEM);
    cudaFuncSetAttribute(k1_gemm, cudaFuncAttributeMaxDynamicSharedMemorySize, K1_SMEM);
    cudaFuncSetAttribute(k3_softmax, cudaFuncAttributeMaxDynamicSharedMemorySize, K3_SMEM);

    dim3 g1(Bdim / 128, Xpad / 128);
    k1r_gemm<<<g1, 256, KR_SMEM>>>(y, styleR);               // 1
    ksplitW<<<WBLKS + Ydim, 256>>>(Wg2, Wmu, Wvar);          // 2
    k0_small<<<Bdim / 8, 256>>>(z, y, bmu, bvar, styleL, out_mu, out_var);  // 3
    k1_gemm<<<g1, 256, K1_SMEM>>>(outx);                     // 4  <- ncu profiles this

    kstats_final<<<(Xdim + 255) / 256, 256>>>(gamma, beta);  // 5
    k3_softmax<<<Bdim, 512, K3_SMEM>>>(outx);                // 6
}

// round 15
// speedup vs baseline: 1.0910x; 1.0702x over previous
#include <cuda_runtime.h>
#include <cuda_bf16.h>
#include <mma.h>
#include <math.h>
#include <stdint.h>

using namespace nvcuda;

#define Bdim 4096
#define Zdim 256
#define Ydim 64
#define Xdim 30000
#define Xpad 30080
#define NBT  32            // number of b-tiles (Bdim/128)
#define BN_EPS 1e-3f

// ---------------- device scratch ----------------
__device__ __nv_bfloat16 g_Ah[Bdim * Zdim], g_Al[Bdim * Zdim];   // zs*tmp_L
__device__ __nv_bfloat16 g_Wh[Xpad * Zdim], g_Wl[Xpad * Zdim];   // W_g2 (padded X)
__device__ float g_R[(size_t)Bdim * Xpad];                       // R = y @ style_R
__device__ float g_WmuT[Ydim * Zdim], g_WvarT[Ydim * Zdim];      // transposed [Y,Z]
__device__ float g_ps[NBT * Xpad], g_pq[NBT * Xpad];             // BN partial sums
__device__ float g_scale[Xdim], g_shift[Xdim];

__device__ __forceinline__ void bsplit(float v, __nv_bfloat16& h, __nv_bfloat16& l) {
    h = __float2bfloat16(v);
    l = __float2bfloat16(v - __bfloat162float(h));
}

__device__ __forceinline__ uint32_t smem_u32(const void* p) {
    uint32_t a;
    asm("{ .reg .u64 t; cvta.to.shared.u64 t, %1; cvt.u32.u64 %0, t; }" : "=r"(a) : "l"(p));
    return a;
}
#define CP_ASYNC16(dst, src) \
    asm volatile("cp.async.cg.shared.global [%0], [%1], 16;" :: "r"(dst), "l"(src))
#define CP_COMMIT() asm volatile("cp.async.commit_group;")
#define CP_WAIT1()  asm volatile("cp.async.wait_group 1;")
#define CP_WAIT0()  asm volatile("cp.async.wait_group 0;")

// ============================================================================
// Launch 1: k1R — R = y @ style_R (bf16x3), self-converting, -> g_R
// ============================================================================
#define RLDA 72
#define RLDB 136
#define R_YH 0
#define R_YL 18432
#define R_SH 36864
#define R_SL 54272
#define KR_SMEM 71680

__global__ __launch_bounds__(256, 2) void k1r_gemm(const float* __restrict__ y,
                                                   const float* __restrict__ SR)
{
    extern __shared__ char smem[];
    __nv_bfloat16* sYh = (__nv_bfloat16*)(smem + R_YH);
    __nv_bfloat16* sYl = (__nv_bfloat16*)(smem + R_YL);
    __nv_bfloat16* sSh = (__nv_bfloat16*)(smem + R_SH);
    __nv_bfloat16* sSl = (__nv_bfloat16*)(smem + R_SL);

    const int b0 = blockIdx.x * 128;
    const int x0 = blockIdx.y * 128;
    const int t  = threadIdx.x;
    const int wid = t >> 5;
    const int wm = wid & 1;
    const int wn = wid >> 1;

    #pragma unroll
    for (int i = 0; i < 8; i++) {
        int u = t + i * 256;
        int row = u >> 4;
        int col = (u & 15) * 4;
        float4 v = *(const float4*)&y[(size_t)(b0 + row) * Ydim + col];
        __nv_bfloat16 h0, h1, h2, h3, l0, l1, l2, l3;
        bsplit(v.x, h0, l0); bsplit(v.y, h1, l1); bsplit(v.z, h2, l2); bsplit(v.w, h3, l3);
        *(ushort4*)&sYh[row * RLDA + col] = make_ushort4(__bfloat16_as_ushort(h0), __bfloat16_as_ushort(h1),
                                                         __bfloat16_as_ushort(h2), __bfloat16_as_ushort(h3));
        *(ushort4*)&sYl[row * RLDA + col] = make_ushort4(__bfloat16_as_ushort(l0), __bfloat16_as_ushort(l1),
                                                         __bfloat16_as_ushort(l2), __bfloat16_as_ushort(l3));
    }
    #pragma unroll
    for (int i = 0; i < 8; i++) {
        int u = t + i * 256;
        int row = u >> 5;
        int col = (u & 31) * 4;
        int x = x0 + col;
        float4 v = make_float4(0.f, 0.f, 0.f, 0.f);
        if (x < Xdim) v = *(const float4*)&SR[(size_t)row * Xdim + x];
        __nv_bfloat16 h0, h1, h2, h3, l0, l1, l2, l3;
        bsplit(v.x, h0, l0); bsplit(v.y, h1, l1); bsplit(v.z, h2, l2); bsplit(v.w, h3, l3);
        *(ushort4*)&sSh[row * RLDB + col] = make_ushort4(__bfloat16_as_ushort(h0), __bfloat16_as_ushort(h1),
                                                         __bfloat16_as_ushort(h2), __bfloat16_as_ushort(h3));
        *(ushort4*)&sSl[row * RLDB + col] = make_ushort4(__bfloat16_as_ushort(l0), __bfloat16_as_ushort(l1),
                                                         __bfloat16_as_ushort(l2), __bfloat16_as_ushort(l3));
    }
    __syncthreads();

    wmma::fragment<wmma::accumulator, 16, 16, 16, float> acc[4][2];
    #pragma unroll
    for (int mi = 0; mi < 4; mi++)
        #pragma unroll
        for (int ni = 0; ni < 2; ni++)
            wmma::fill_fragment(acc[mi][ni], 0.f);

    #pragma unroll
    for (int kk = 0; kk < Ydim; kk += 16) {
        wmma::fragment<wmma::matrix_b, 16, 16, 16, __nv_bfloat16, wmma::row_major> fbh[2], fbl[2];
        #pragma unroll
        for (int ni = 0; ni < 2; ni++) {
            wmma::load_matrix_sync(fbh[ni], sSh + kk * RLDB + wn * 32 + ni * 16, RLDB);
            wmma::load_matrix_sync(fbl[ni], sSl + kk * RLDB + wn * 32 + ni * 16, RLDB);
        }
        #pragma unroll
        for (int mi = 0; mi < 4; mi++) {
            wmma::fragment<wmma::matrix_a, 16, 16, 16, __nv_bfloat16, wmma::row_major> fah, fal;
            wmma::load_matrix_sync(fah, sYh + (wm * 64 + mi * 16) * RLDA + kk, RLDA);
            wmma::load_matrix_sync(fal, sYl + (wm * 64 + mi * 16) * RLDA + kk, RLDA);
            #pragma unroll
            for (int ni = 0; ni < 2; ni++) {
                wmma::mma_sync(acc[mi][ni], fah, fbh[ni], acc[mi][ni]);
                wmma::mma_sync(acc[mi][ni], fah, fbl[ni], acc[mi][ni]);
                wmma::mma_sync(acc[mi][ni], fal, fbh[ni], acc[mi][ni]);
            }
        }
    }
    #pragma unroll
    for (int mi = 0; mi < 4; mi++)
        #pragma unroll
        for (int ni = 0; ni < 2; ni++)
            wmma::store_matrix_sync(
                &g_R[(size_t)(b0 + wm * 64 + mi * 16) * Xpad + x0 + wn * 32 + ni * 16],
                acc[mi][ni], Xpad, wmma::mem_row_major);
}

// ============================================================================
// Launch 2: ksplitW — W_g2 -> bf16 hi/lo; tail: Wmu/Wvar^T
// ============================================================================
#define WBLKS (Xpad * Zdim / 4 / 256)
__global__ __launch_bounds__(256) void ksplitW(const float* __restrict__ W,
                                               const float* __restrict__ Wmu,
                                               const float* __restrict__ Wvar) {
    if (blockIdx.x >= WBLKS) {
        int j = blockIdx.x - WBLKS, t = threadIdx.x;
        g_WmuT[j * Zdim + t]  = Wmu[t * Ydim + j];
        g_WvarT[j * Zdim + t] = Wvar[t * Ydim + j];
        return;
    }
    int u = blockIdx.x * 256 + threadIdx.x;
    int x = u >> 6;
    int kg = (u & 63) * 4;
    float4 v = make_float4(0.f, 0.f, 0.f, 0.f);
    if (x < Xdim) v = *(const float4*)&W[(size_t)x * Zdim + kg];
    __nv_bfloat16 h0, h1, h2, h3, l0, l1, l2, l3;
    bsplit(v.x, h0, l0); bsplit(v.y, h1, l1); bsplit(v.z, h2, l2); bsplit(v.w, h3, l3);
    *(ushort4*)&g_Wh[(size_t)u * 4] = make_ushort4(__bfloat16_as_ushort(h0), __bfloat16_as_ushort(h1),
                                                   __bfloat16_as_ushort(h2), __bfloat16_as_ushort(h3));
    *(ushort4*)&g_Wl[(size_t)u * 4] = make_ushort4(__bfloat16_as_ushort(l0), __bfloat16_as_ushort(l1),
                                                   __bfloat16_as_ushort(l2), __bfloat16_as_ushort(l3));
}

// ============================================================================
// Launch 3: K0 — 8 batch rows per block; coalesced [Y,Z] weight streams.
// ============================================================================
__global__ __launch_bounds__(256) void k0_small(
    const float* __restrict__ z, const float* __restrict__ y,
    const float* __restrict__ bmu, const float* __restrict__ bvar,
    const float* __restrict__ styleL,
    float* __restrict__ out_mu, float* __restrict__ out_var)
{
    __shared__ float ys[8][Ydim];
    __shared__ float stl[8][Zdim];
    const int b0 = blockIdx.x * 8;
    const int t  = threadIdx.x;

    #pragma unroll
    for (int i = 0; i < 2; i++) {
        int u = t + i * 256;
        ys[u >> 6][u & 63] = y[b0 * Ydim + u];
    }
    __syncthreads();

    float bm = bmu[t], bv = bvar[t];
    float mu[8] = {}, va[8] = {}, tl[8] = {};
    #pragma unroll 4
    for (int j = 0; j < Ydim; j++) {
        float wm = g_WmuT[j * Zdim + t];
        float wv = g_WvarT[j * Zdim + t];
        float sl = styleL[j * Zdim + t];
        #pragma unroll
        for (int r = 0; r < 8; r++) {
            float yj = ys[r][j];
            mu[r] = fmaf(yj, wm, mu[r]);
            va[r] = fmaf(yj, wv, va[r]);
            tl[r] = fmaf(yj, sl, tl[r]);
        }
    }
    #pragma unroll
    for (int r = 0; r < 8; r++) {
        out_mu[(b0 + r) * Zdim + t] = mu[r] + bm;
        float xv = va[r] + bv;
        out_var[(b0 + r) * Zdim + t] = fmaxf(xv, 0.f) + log1pf(__expf(-fabsf(xv)));
        stl[r][t] = tl[r];
    }
    __syncthreads();

    const int w = t >> 5, l = t & 31;
    const float* zr = z + (size_t)(b0 + w) * Zdim;
    float zv[8];
    float m = -1e30f;
    #pragma unroll
    for (int k = 0; k < 8; k++) { zv[k] = zr[l + 32 * k]; m = fmaxf(m, zv[k]); }
    #pragma unroll
    for (int o = 16; o; o >>= 1) m = fmaxf(m, __shfl_xor_sync(0xFFFFFFFFu, m, o));
    float s = 0.f;
    #pragma unroll
    for (int k = 0; k < 8; k++) { zv[k] = __expf(zv[k] - m); s += zv[k]; }
    #pragma unroll
    for (int o = 16; o; o >>= 1) s += __shfl_xor_sync(0xFFFFFFFFu, s, o);
    float inv = 1.f / s;
    #pragma unroll
    for (int k = 0; k < 8; k++) {
        float a = zv[k] * inv * stl[w][l + 32 * k];
        __nv_bfloat16 ah, al;
        bsplit(a, ah, al);
        int idx = (b0 + w) * Zdim + l + 32 * k;
        g_Ah[idx] = ah;
        g_Al[idx] = al;
    }
}

// ============================================================================
// Launch 4: K1C — C = A @ W_g2^T (bf16x3), R7 mainloop (pass-outer MMA order).
//   Epilogue: h = C * R(g_R) -> outx ; smem-reduced BN partials -> g_ps/g_pq.
// ============================================================================
#define LDA 56
#define OFF_AL 14336
#define OFF_WH 28672
#define OFF_WL 43008
#define BUF_STRIDE 57344
#define K1_SMEM (2 * BUF_STRIDE)
#define SC_LD 132
#define SS_OFF 67584
#define SQ_OFF (67584 + 4096)

__global__ __launch_bounds__(256, 2) void k1_gemm(float* __restrict__ outx)
{
    extern __shared__ char smem[];
    const int bt = blockIdx.x;
    const int b0 = bt * 128;
    const int x0 = blockIdx.y * 128;
    const int t  = threadIdx.x;
    const int wid = t >> 5;
    const int wm = wid & 1;
    const int wn = wid >> 1;

    wmma::fragment<wmma::accumulator, 16, 16, 16, float> accC[4][2];
    #pragma unroll
    for (int mi = 0; mi < 4; mi++)
        #pragma unroll
        for (int ni = 0; ni < 2; ni++)
            wmma::fill_fragment(accC[mi][ni], 0.f);

    const uint32_t sbase = smem_u32(smem);

    auto stage = [&](int c, int p) {
        const int kc = c * 32;
        const uint32_t bb = sbase + p * BUF_STRIDE;
        #pragma unroll
        for (int i = 0; i < 2; i++) {
            int u = t + i * 256;
            int row = u >> 2;
            int cg = (u & 3) * 8;
            uint32_t so = (row * LDA + cg) * 2;
            CP_ASYNC16(bb + so,           &g_Ah[(size_t)(b0 + row) * Zdim + kc + cg]);
            CP_ASYNC16(bb + OFF_AL + so,  &g_Al[(size_t)(b0 + row) * Zdim + kc + cg]);
            CP_ASYNC16(bb + OFF_WH + so,  &g_Wh[(size_t)(x0 + row) * Zdim + kc + cg]);
            CP_ASYNC16(bb + OFF_WL + so,  &g_Wl[(size_t)(x0 + row) * Zdim + kc + cg]);
        }
        CP_COMMIT();
    };

    stage(0, 0);
    for (int c = 0; c < 8; c++) {
        if (c < 7) { stage(c + 1, (c + 1) & 1); CP_WAIT1(); }
        else       { CP_WAIT0(); }
        __syncthreads();

        char* buf = smem + (c & 1) * BUF_STRIDE;
        __nv_bfloat16* sAh = (__nv_bfloat16*)buf;
        __nv_bfloat16* sAl = (__nv_bfloat16*)(buf + OFF_AL);
        __nv_bfloat16* sWh = (__nv_bfloat16*)(buf + OFF_WH);
        __nv_bfloat16* sWl = (__nv_bfloat16*)(buf + OFF_WL);

        #pragma unroll
        for (int k2 = 0; k2 < 32; k2 += 16) {
            wmma::fragment<wmma::matrix_b, 16, 16, 16, __nv_bfloat16, wmma::col_major> fbh[2], fbl[2];
            #pragma unroll
            for (int ni = 0; ni < 2; ni++) {
                wmma::load_matrix_sync(fbh[ni], sWh + (wn * 32 + ni * 16) * LDA + k2, LDA);
                wmma::load_matrix_sync(fbl[ni], sWl + (wn * 32 + ni * 16) * LDA + k2, LDA);
            }
            #pragma unroll
            for (int mi = 0; mi < 4; mi++) {
                wmma::fragment<wmma::matrix_a, 16, 16, 16, __nv_bfloat16, wmma::row_major> fah, fal;
                wmma::load_matrix_sync(fah, sAh + (wm * 64 + mi * 16) * LDA + k2, LDA);
                wmma::load_matrix_sync(fal, sAl + (wm * 64 + mi * 16) * LDA + k2, LDA);
                // pass-outer / ni-inner: dependent acc reuses are 2 ops apart
                #pragma unroll
                for (int ni = 0; ni < 2; ni++)
                    wmma::mma_sync(accC[mi][ni], fah, fbh[ni], accC[mi][ni]);
                #pragma unroll
                for (int ni = 0; ni < 2; ni++)
                    wmma::mma_sync(accC[mi][ni], fah, fbl[ni], accC[mi][ni]);
                #pragma unroll
                for (int ni = 0; ni < 2; ni++)
                    wmma::mma_sync(accC[mi][ni], fal, fbh[ni], accC[mi][ni]);
            }
        }
        __syncthreads();
    }

    // ---------------- epilogue: C -> smem, h = C*R -> outx, BN partials -----
    float* sC = (float*)smem;
    float* sS = (float*)(smem + SS_OFF);
    float* sQ = (float*)(smem + SQ_OFF);
    #pragma unroll
    for (int mi = 0; mi < 4; mi++)
        #pragma unroll
        for (int ni = 0; ni < 2; ni++)
            wmma::store_matrix_sync(&sC[(wm * 64 + mi * 16) * SC_LD + wn * 32 + ni * 16],
                                    accC[mi][ni], SC_LD, wmma::mem_row_major);
    __syncthreads();

    {
        const int lc = (t & 31) * 4;
        const int r0 = t >> 5;
        const int x  = x0 + lc;
        float s0 = 0.f, s1 = 0.f, s2 = 0.f, s3 = 0.f;
        float q0 = 0.f, q1 = 0.f, q2 = 0.f, q3 = 0.f;
        if (x < Xdim) {
            #pragma unroll
            for (int i = 0; i < 16; i++) {
                int row = r0 + i * 8;
                float4 cv = *(float4*)&sC[row * SC_LD + lc];
                float4 rv = *(const float4*)&g_R[(size_t)(b0 + row) * Xpad + x];
                cv.x *= rv.x; cv.y *= rv.y; cv.z *= rv.z; cv.w *= rv.w;
                *(float4*)&outx[(size_t)(b0 + row) * Xdim + x] = cv;
                s0 += cv.x; q0 = fmaf(cv.x, cv.x, q0);
                s1 += cv.y; q1 = fmaf(cv.y, cv.y, q1);
                s2 += cv.z; q2 = fmaf(cv.z, cv.z, q2);
                s3 += cv.w; q3 = fmaf(cv.w, cv.w, q3);
            }
        }
        *(float4*)&sS[r0 * 128 + lc] = make_float4(s0, s1, s2, s3);
        *(float4*)&sQ[r0 * 128 + lc] = make_float4(q0, q1, q2, q3);
    }
    __syncthreads();

    if (t < 32) {
        const int lc = t * 4;
        const int x  = x0 + lc;
        if (x < Xdim) {
            float4 S = make_float4(0.f, 0.f, 0.f, 0.f);
            float4 Q = make_float4(0.f, 0.f, 0.f, 0.f);
            #pragma unroll
            for (int r = 0; r < 8; r++) {
                float4 a = *(float4*)&sS[r * 128 + lc];
                float4 b = *(float4*)&sQ[r * 128 + lc];
                S.x += a.x; S.y += a.y; S.z += a.z; S.w += a.w;
                Q.x += b.x; Q.y += b.y; Q.z += b.z; Q.w += b.w;
            }
            *(float4*)&g_ps[(size_t)bt * Xpad + x] = S;
            *(float4*)&g_pq[(size_t)bt * Xpad + x] = Q;
        }
    }
}

// ============================================================================
// Launch 5: kstats_final — reduce 32 partials -> BN scale/shift
// ============================================================================
__global__ __launch_bounds__(256) void kstats_final(
    const float* __restrict__ gamma, const float* __restrict__ beta)
{
    int x = blockIdx.x * 256 + threadIdx.x;
    if (x >= Xdim) return;
    float s = 0.f, q = 0.f;
    #pragma unroll
    for (int j = 0; j < NBT; j++) {
        s += g_ps[(size_t)j * Xpad + x];
        q += g_pq[(size_t)j * Xpad + x];
    }
    const float invB = 1.f / (float)Bdim;
    float mean = s * invB;
    float var  = q * invB - mean * mean;
    float inv  = rsqrtf(var + BN_EPS);
    float sc   = inv * gamma[x];
    g_scale[x] = sc;
    g_shift[x] = beta[x] - mean * sc;
}

// ============================================================================
// Launch 6: K3 — affine + softmax; online 2-phase, logits cached in smem.
//   1024 threads (32 warps/SM) for doubled memory-level parallelism.
// ============================================================================
#define K3_SMEM (Xdim * 4)
#define K3_THREADS 1024

__global__ __launch_bounds__(K3_THREADS) void k3_softmax(float* __restrict__ outx)
{
    extern __shared__ float sa[];
    const int b = blockIdx.x;
    const int t = threadIdx.x;
    float4* row = (float4*)(outx + (size_t)b * Xdim);
    const float4* sc4 = (const float4*)g_scale;
    const float4* sh4 = (const float4*)g_shift;
    const int N4 = Xdim / 4;

    float m = -1e30f, s = 0.f;
    for (int i = t; i < N4; i += K3_THREADS) {
        float4 v = row[i], sc = sc4[i], sh = sh4[i];
        float4 a;
        a.x = fmaf(v.x, sc.x, sh.x);
        a.y = fmaf(v.y, sc.y, sh.y);
        a.z = fmaf(v.z, sc.z, sh.z);
        a.w = fmaf(v.w, sc.w, sh.w);
        *(float4*)&sa[i * 4] = a;
        float mv = fmaxf(fmaxf(a.x, a.y), fmaxf(a.z, a.w));
        float nm = fmaxf(m, mv);
        s = s * __expf(m - nm) + __expf(a.x - nm) + __expf(a.y - nm)
          + __expf(a.z - nm) + __expf(a.w - nm);
        m = nm;
    }
    #pragma unroll
    for (int o = 16; o; o >>= 1) {
        float mo = __shfl_xor_sync(0xFFFFFFFFu, m, o);
        float so = __shfl_xor_sync(0xFFFFFFFFu, s, o);
        float nm = fmaxf(m, mo);
        s = s * __expf(m - nm) + so * __expf(mo - nm);
        m = nm;
    }
    __shared__ float sm[32], ss[32];
    int w = t >> 5, l = t & 31;
    if (l == 0) { sm[w] = m; ss[w] = s; }
    __syncthreads();
    if (w == 0) {
        m = sm[l];
        s = ss[l];
        #pragma unroll
        for (int o = 16; o; o >>= 1) {
            float mo = __shfl_xor_sync(0xFFFFFFFFu, m, o);
            float so = __shfl_xor_sync(0xFFFFFFFFu, s, o);
            float nm = fmaxf(m, mo);
            s = s * __expf(m - nm) + so * __expf(mo - nm);
            m = nm;
        }
        if (l == 0) { sm[0] = m; ss[0] = s; }
    }
    __syncthreads();
    const float M = sm[0];
    const float invS = 1.f / ss[0];

    for (int i = t; i < N4; i += K3_THREADS) {
        float4 a = *(float4*)&sa[i * 4];
        float4 o;
        o.x = __expf(a.x - M) * invS;
        o.y = __expf(a.y - M) * invS;
        o.z = __expf(a.z - M) * invS;
        o.w = __expf(a.w - M) * invS;
        row[i] = o;
    }
}

// ============================================================================
extern "C" void kernel_launch(void* const* d_in, const int* in_sizes, int n_in,
                              void* d_out, int out_size)
{
    const float* z      = (const float*)d_in[0];
    const float* y      = (const float*)d_in[1];
    const float* Wmu    = (const float*)d_in[2];
    const float* bmu    = (const float*)d_in[3];
    const float* Wvar   = (const float*)d_in[4];
    const float* bvar   = (const float*)d_in[5];
    const float* Wg2    = (const float*)d_in[6];
    const float* styleL = (const float*)d_in[7];
    const float* styleR = (const float*)d_in[8];
    const float* gamma  = (const float*)d_in[9];
    const float* beta   = (const float*)d_in[10];

    float* out     = (float*)d_out;
    float* out_mu  = out;
    float* out_var = out + (size_t)Bdim * Zdim;
    float* outx    = out + (size_t)2 * Bdim * Zdim;

    cudaFuncSetAttribute(k1r_gemm, cudaFuncAttributeMaxDynamicSharedMemorySize, KR_SMEM);
    cudaFuncSetAttribute(k1_gemm, cudaFuncAttributeMaxDynamicSharedMemorySize, K1_SMEM);
    cudaFuncSetAttribute(k3_softmax, cudaFuncAttributeMaxDynamicSharedMemorySize, K3_SMEM);

    dim3 g1(Bdim / 128, Xpad / 128);
    k1r_gemm<<<g1, 256, KR_SMEM>>>(y, styleR);               // 1
    ksplitW<<<WBLKS + Ydim, 256>>>(Wg2, Wmu, Wvar);          // 2
    k0_small<<<Bdim / 8, 256>>>(z, y, bmu, bvar, styleL, out_mu, out_var);  // 3
    k1_gemm<<<g1, 256, K1_SMEM>>>(outx);                     // 4  <- ncu profiles this

    kstats_final<<<(Xdim + 255) / 256, 256>>>(gamma, beta);  // 5
    k3_softmax<<<Bdim, K3_THREADS, K3_SMEM>>>(outx);         // 6
}

// round 16
// speedup vs baseline: 1.1023x; 1.0103x over previous
#include <cuda_runtime.h>
#include <cuda_bf16.h>
#include <mma.h>
#include <math.h>
#include <stdint.h>

using namespace nvcuda;

#define Bdim 4096
#define Zdim 256
#define Ydim 64
#define Xdim 30000
#define Xpad 30080
#define NBT  32            // number of b-tiles (Bdim/128)
#define BN_EPS 1e-3f

// ---------------- device scratch ----------------
__device__ __nv_bfloat16 g_Ah[Bdim * Zdim], g_Al[Bdim * Zdim];   // zs*tmp_L
__device__ __nv_bfloat16 g_Wh[Xpad * Zdim], g_Wl[Xpad * Zdim];   // W_g2 (padded X)
__device__ float g_R[(size_t)Bdim * Xpad];                       // R = y @ style_R
__device__ float g_WmuT[Ydim * Zdim], g_WvarT[Ydim * Zdim];      // transposed [Y,Z]
__device__ float g_ps[NBT * Xpad], g_pq[NBT * Xpad];             // BN partial sums
__device__ float g_scale[Xdim], g_shift[Xdim];

__device__ __forceinline__ void bsplit(float v, __nv_bfloat16& h, __nv_bfloat16& l) {
    h = __float2bfloat16(v);
    l = __float2bfloat16(v - __bfloat162float(h));
}

__device__ __forceinline__ uint32_t smem_u32(const void* p) {
    uint32_t a;
    asm("{ .reg .u64 t; cvta.to.shared.u64 t, %1; cvt.u32.u64 %0, t; }" : "=r"(a) : "l"(p));
    return a;
}
#define CP_ASYNC16(dst, src) \
    asm volatile("cp.async.cg.shared.global [%0], [%1], 16;" :: "r"(dst), "l"(src))
#define CP_COMMIT() asm volatile("cp.async.commit_group;")
#define CP_WAIT1()  asm volatile("cp.async.wait_group 1;")
#define CP_WAIT0()  asm volatile("cp.async.wait_group 0;")

// ============================================================================
// k1R — R = y @ style_R (bf16x3), self-converting, -> g_R   [side stream]
// ============================================================================
#define RLDA 72
#define RLDB 136
#define R_YH 0
#define R_YL 18432
#define R_SH 36864
#define R_SL 54272
#define KR_SMEM 71680

__global__ __launch_bounds__(256, 2) void k1r_gemm(const float* __restrict__ y,
                                                   const float* __restrict__ SR)
{
    extern __shared__ char smem[];
    __nv_bfloat16* sYh = (__nv_bfloat16*)(smem + R_YH);
    __nv_bfloat16* sYl = (__nv_bfloat16*)(smem + R_YL);
    __nv_bfloat16* sSh = (__nv_bfloat16*)(smem + R_SH);
    __nv_bfloat16* sSl = (__nv_bfloat16*)(smem + R_SL);

    const int b0 = blockIdx.x * 128;
    const int x0 = blockIdx.y * 128;
    const int t  = threadIdx.x;
    const int wid = t >> 5;
    const int wm = wid & 1;
    const int wn = wid >> 1;

    #pragma unroll
    for (int i = 0; i < 8; i++) {
        int u = t + i * 256;
        int row = u >> 4;
        int col = (u & 15) * 4;
        float4 v = *(const float4*)&y[(size_t)(b0 + row) * Ydim + col];
        __nv_bfloat16 h0, h1, h2, h3, l0, l1, l2, l3;
        bsplit(v.x, h0, l0); bsplit(v.y, h1, l1); bsplit(v.z, h2, l2); bsplit(v.w, h3, l3);
        *(ushort4*)&sYh[row * RLDA + col] = make_ushort4(__bfloat16_as_ushort(h0), __bfloat16_as_ushort(h1),
                                                         __bfloat16_as_ushort(h2), __bfloat16_as_ushort(h3));
        *(ushort4*)&sYl[row * RLDA + col] = make_ushort4(__bfloat16_as_ushort(l0), __bfloat16_as_ushort(l1),
                                                         __bfloat16_as_ushort(l2), __bfloat16_as_ushort(l3));
    }
    #pragma unroll
    for (int i = 0; i < 8; i++) {
        int u = t + i * 256;
        int row = u >> 5;
        int col = (u & 31) * 4;
        int x = x0 + col;
        float4 v = make_float4(0.f, 0.f, 0.f, 0.f);
        if (x < Xdim) v = *(const float4*)&SR[(size_t)row * Xdim + x];
        __nv_bfloat16 h0, h1, h2, h3, l0, l1, l2, l3;
        bsplit(v.x, h0, l0); bsplit(v.y, h1, l1); bsplit(v.z, h2, l2); bsplit(v.w, h3, l3);
        *(ushort4*)&sSh[row * RLDB + col] = make_ushort4(__bfloat16_as_ushort(h0), __bfloat16_as_ushort(h1),
                                                         __bfloat16_as_ushort(h2), __bfloat16_as_ushort(h3));
        *(ushort4*)&sSl[row * RLDB + col] = make_ushort4(__bfloat16_as_ushort(l0), __bfloat16_as_ushort(l1),
                                                         __bfloat16_as_ushort(l2), __bfloat16_as_ushort(l3));
    }
    __syncthreads();

    wmma::fragment<wmma::accumulator, 16, 16, 16, float> acc[4][2];
    #pragma unroll
    for (int mi = 0; mi < 4; mi++)
        #pragma unroll
        for (int ni = 0; ni < 2; ni++)
            wmma::fill_fragment(acc[mi][ni], 0.f);

    #pragma unroll
    for (int kk = 0; kk < Ydim; kk += 16) {
        wmma::fragment<wmma::matrix_b, 16, 16, 16, __nv_bfloat16, wmma::row_major> fbh[2], fbl[2];
        #pragma unroll
        for (int ni = 0; ni < 2; ni++) {
            wmma::load_matrix_sync(fbh[ni], sSh + kk * RLDB + wn * 32 + ni * 16, RLDB);
            wmma::load_matrix_sync(fbl[ni], sSl + kk * RLDB + wn * 32 + ni * 16, RLDB);
        }
        #pragma unroll
        for (int mi = 0; mi < 4; mi++) {
            wmma::fragment<wmma::matrix_a, 16, 16, 16, __nv_bfloat16, wmma::row_major> fah, fal;
            wmma::load_matrix_sync(fah, sYh + (wm * 64 + mi * 16) * RLDA + kk, RLDA);
            wmma::load_matrix_sync(fal, sYl + (wm * 64 + mi * 16) * RLDA + kk, RLDA);
            #pragma unroll
            for (int ni = 0; ni < 2; ni++) {
                wmma::mma_sync(acc[mi][ni], fah, fbh[ni], acc[mi][ni]);
                wmma::mma_sync(acc[mi][ni], fah, fbl[ni], acc[mi][ni]);
                wmma::mma_sync(acc[mi][ni], fal, fbh[ni], acc[mi][ni]);
            }
        }
    }
    #pragma unroll
    for (int mi = 0; mi < 4; mi++)
        #pragma unroll
        for (int ni = 0; ni < 2; ni++)
            wmma::store_matrix_sync(
                &g_R[(size_t)(b0 + wm * 64 + mi * 16) * Xpad + x0 + wn * 32 + ni * 16],
                acc[mi][ni], Xpad, wmma::mem_row_major);
}

// ============================================================================
// ksplitW — W_g2 -> bf16 hi/lo; tail: Wmu/Wvar^T   [main stream]
// ============================================================================
#define WBLKS (Xpad * Zdim / 4 / 256)
__global__ __launch_bounds__(256) void ksplitW(const float* __restrict__ W,
                                               const float* __restrict__ Wmu,
                                               const float* __restrict__ Wvar) {
    if (blockIdx.x >= WBLKS) {
        int j = blockIdx.x - WBLKS, t = threadIdx.x;
        g_WmuT[j * Zdim + t]  = Wmu[t * Ydim + j];
        g_WvarT[j * Zdim + t] = Wvar[t * Ydim + j];
        return;
    }
    int u = blockIdx.x * 256 + threadIdx.x;
    int x = u >> 6;
    int kg = (u & 63) * 4;
    float4 v = make_float4(0.f, 0.f, 0.f, 0.f);
    if (x < Xdim) v = *(const float4*)&W[(size_t)x * Zdim + kg];
    __nv_bfloat16 h0, h1, h2, h3, l0, l1, l2, l3;
    bsplit(v.x, h0, l0); bsplit(v.y, h1, l1); bsplit(v.z, h2, l2); bsplit(v.w, h3, l3);
    *(ushort4*)&g_Wh[(size_t)u * 4] = make_ushort4(__bfloat16_as_ushort(h0), __bfloat16_as_ushort(h1),
                                                   __bfloat16_as_ushort(h2), __bfloat16_as_ushort(h3));
    *(ushort4*)&g_Wl[(size_t)u * 4] = make_ushort4(__bfloat16_as_ushort(l0), __bfloat16_as_ushort(l1),
                                                   __bfloat16_as_ushort(l2), __bfloat16_as_ushort(l3));
}

// ============================================================================
// K0 — 8 batch rows per block; coalesced [Y,Z] weight streams.  [main stream]
// ============================================================================
__global__ __launch_bounds__(256) void k0_small(
    const float* __restrict__ z, const float* __restrict__ y,
    const float* __restrict__ bmu, const float* __restrict__ bvar,
    const float* __restrict__ styleL,
    float* __restrict__ out_mu, float* __restrict__ out_var)
{
    __shared__ float ys[8][Ydim];
    __shared__ float stl[8][Zdim];
    const int b0 = blockIdx.x * 8;
    const int t  = threadIdx.x;

    #pragma unroll
    for (int i = 0; i < 2; i++) {
        int u = t + i * 256;
        ys[u >> 6][u & 63] = y[b0 * Ydim + u];
    }
    __syncthreads();

    float bm = bmu[t], bv = bvar[t];
    float mu[8] = {}, va[8] = {}, tl[8] = {};
    #pragma unroll 4
    for (int j = 0; j < Ydim; j++) {
        float wm = g_WmuT[j * Zdim + t];
        float wv = g_WvarT[j * Zdim + t];
        float sl = styleL[j * Zdim + t];
        #pragma unroll
        for (int r = 0; r < 8; r++) {
            float yj = ys[r][j];
            mu[r] = fmaf(yj, wm, mu[r]);
            va[r] = fmaf(yj, wv, va[r]);
            tl[r] = fmaf(yj, sl, tl[r]);
        }
    }
    #pragma unroll
    for (int r = 0; r < 8; r++) {
        out_mu[(b0 + r) * Zdim + t] = mu[r] + bm;
        float xv = va[r] + bv;
        out_var[(b0 + r) * Zdim + t] = fmaxf(xv, 0.f) + log1pf(__expf(-fabsf(xv)));
        stl[r][t] = tl[r];
    }
    __syncthreads();

    const int w = t >> 5, l = t & 31;
    const float* zr = z + (size_t)(b0 + w) * Zdim;
    float zv[8];
    float m = -1e30f;
    #pragma unroll
    for (int k = 0; k < 8; k++) { zv[k] = zr[l + 32 * k]; m = fmaxf(m, zv[k]); }
    #pragma unroll
    for (int o = 16; o; o >>= 1) m = fmaxf(m, __shfl_xor_sync(0xFFFFFFFFu, m, o));
    float s = 0.f;
    #pragma unroll
    for (int k = 0; k < 8; k++) { zv[k] = __expf(zv[k] - m); s += zv[k]; }
    #pragma unroll
    for (int o = 16; o; o >>= 1) s += __shfl_xor_sync(0xFFFFFFFFu, s, o);
    float inv = 1.f / s;
    #pragma unroll
    for (int k = 0; k < 8; k++) {
        float a = zv[k] * inv * stl[w][l + 32 * k];
        __nv_bfloat16 ah, al;
        bsplit(a, ah, al);
        int idx = (b0 + w) * Zdim + l + 32 * k;
        g_Ah[idx] = ah;
        g_Al[idx] = al;
    }
}

// ============================================================================
// K1C — C = A @ W_g2^T (bf16x3), R7 mainloop (pass-outer MMA order).
//   Epilogue: h = C * R(g_R) -> outx ; smem-reduced BN partials -> g_ps/g_pq.
// ============================================================================
#define LDA 56
#define OFF_AL 14336
#define OFF_WH 28672
#define OFF_WL 43008
#define BUF_STRIDE 57344
#define K1_SMEM (2 * BUF_STRIDE)
#define SC_LD 132
#define SS_OFF 67584
#define SQ_OFF (67584 + 4096)

__global__ __launch_bounds__(256, 2) void k1_gemm(float* __restrict__ outx)
{
    extern __shared__ char smem[];
    const int bt = blockIdx.x;
    const int b0 = bt * 128;
    const int x0 = blockIdx.y * 128;
    const int t  = threadIdx.x;
    const int wid = t >> 5;
    const int wm = wid & 1;
    const int wn = wid >> 1;

    wmma::fragment<wmma::accumulator, 16, 16, 16, float> accC[4][2];
    #pragma unroll
    for (int mi = 0; mi < 4; mi++)
        #pragma unroll
        for (int ni = 0; ni < 2; ni++)
            wmma::fill_fragment(accC[mi][ni], 0.f);

    const uint32_t sbase = smem_u32(smem);

    auto stage = [&](int c, int p) {
        const int kc = c * 32;
        const uint32_t bb = sbase + p * BUF_STRIDE;
        #pragma unroll
        for (int i = 0; i < 2; i++) {
            int u = t + i * 256;
            int row = u >> 2;
            int cg = (u & 3) * 8;
            uint32_t so = (row * LDA + cg) * 2;
            CP_ASYNC16(bb + so,           &g_Ah[(size_t)(b0 + row) * Zdim + kc + cg]);
            CP_ASYNC16(bb + OFF_AL + so,  &g_Al[(size_t)(b0 + row) * Zdim + kc + cg]);
            CP_ASYNC16(bb + OFF_WH + so,  &g_Wh[(size_t)(x0 + row) * Zdim + kc + cg]);
            CP_ASYNC16(bb + OFF_WL + so,  &g_Wl[(size_t)(x0 + row) * Zdim + kc + cg]);
        }
        CP_COMMIT();
    };

    stage(0, 0);
    for (int c = 0; c < 8; c++) {
        if (c < 7) { stage(c + 1, (c + 1) & 1); CP_WAIT1(); }
        else       { CP_WAIT0(); }
        __syncthreads();

        char* buf = smem + (c & 1) * BUF_STRIDE;
        __nv_bfloat16* sAh = (__nv_bfloat16*)buf;
        __nv_bfloat16* sAl = (__nv_bfloat16*)(buf + OFF_AL);
        __nv_bfloat16* sWh = (__nv_bfloat16*)(buf + OFF_WH);
        __nv_bfloat16* sWl = (__nv_bfloat16*)(buf + OFF_WL);

        #pragma unroll
        for (int k2 = 0; k2 < 32; k2 += 16) {
            wmma::fragment<wmma::matrix_b, 16, 16, 16, __nv_bfloat16, wmma::col_major> fbh[2], fbl[2];
            #pragma unroll
            for (int ni = 0; ni < 2; ni++) {
                wmma::load_matrix_sync(fbh[ni], sWh + (wn * 32 + ni * 16) * LDA + k2, LDA);
                wmma::load_matrix_sync(fbl[ni], sWl + (wn * 32 + ni * 16) * LDA + k2, LDA);
            }
            #pragma unroll
            for (int mi = 0; mi < 4; mi++) {
                wmma::fragment<wmma::matrix_a, 16, 16, 16, __nv_bfloat16, wmma::row_major> fah, fal;
                wmma::load_matrix_sync(fah, sAh + (wm * 64 + mi * 16) * LDA + k2, LDA);
                wmma::load_matrix_sync(fal, sAl + (wm * 64 + mi * 16) * LDA + k2, LDA);
                // pass-outer / ni-inner: dependent acc reuses are 2 ops apart
                #pragma unroll
                for (int ni = 0; ni < 2; ni++)
                    wmma::mma_sync(accC[mi][ni], fah, fbh[ni], accC[mi][ni]);
                #pragma unroll
                for (int ni = 0; ni < 2; ni++)
                    wmma::mma_sync(accC[mi][ni], fah, fbl[ni], accC[mi][ni]);
                #pragma unroll
                for (int ni = 0; ni < 2; ni++)
                    wmma::mma_sync(accC[mi][ni], fal, fbh[ni], accC[mi][ni]);
            }
        }
        __syncthreads();
    }

    // ---------------- epilogue: C -> smem, h = C*R -> outx, BN partials -----
    float* sC = (float*)smem;
    float* sS = (float*)(smem + SS_OFF);
    float* sQ = (float*)(smem + SQ_OFF);
    #pragma unroll
    for (int mi = 0; mi < 4; mi++)
        #pragma unroll
        for (int ni = 0; ni < 2; ni++)
            wmma::store_matrix_sync(&sC[(wm * 64 + mi * 16) * SC_LD + wn * 32 + ni * 16],
                                    accC[mi][ni], SC_LD, wmma::mem_row_major);
    __syncthreads();

    {
        const int lc = (t & 31) * 4;
        const int r0 = t >> 5;
        const int x  = x0 + lc;
        float s0 = 0.f, s1 = 0.f, s2 = 0.f, s3 = 0.f;
        float q0 = 0.f, q1 = 0.f, q2 = 0.f, q3 = 0.f;
        if (x < Xdim) {
            #pragma unroll
            for (int i = 0; i < 16; i++) {
                int row = r0 + i * 8;
                float4 cv = *(float4*)&sC[row * SC_LD + lc];
                float4 rv = *(const float4*)&g_R[(size_t)(b0 + row) * Xpad + x];
                cv.x *= rv.x; cv.y *= rv.y; cv.z *= rv.z; cv.w *= rv.w;
                *(float4*)&outx[(size_t)(b0 + row) * Xdim + x] = cv;
                s0 += cv.x; q0 = fmaf(cv.x, cv.x, q0);
                s1 += cv.y; q1 = fmaf(cv.y, cv.y, q1);
                s2 += cv.z; q2 = fmaf(cv.z, cv.z, q2);
                s3 += cv.w; q3 = fmaf(cv.w, cv.w, q3);
            }
        }
        *(float4*)&sS[r0 * 128 + lc] = make_float4(s0, s1, s2, s3);
        *(float4*)&sQ[r0 * 128 + lc] = make_float4(q0, q1, q2, q3);
    }
    __syncthreads();

    if (t < 32) {
        const int lc = t * 4;
        const int x  = x0 + lc;
        if (x < Xdim) {
            float4 S = make_float4(0.f, 0.f, 0.f, 0.f);
            float4 Q = make_float4(0.f, 0.f, 0.f, 0.f);
            #pragma unroll
            for (int r = 0; r < 8; r++) {
                float4 a = *(float4*)&sS[r * 128 + lc];
                float4 b = *(float4*)&sQ[r * 128 + lc];
                S.x += a.x; S.y += a.y; S.z += a.z; S.w += a.w;
                Q.x += b.x; Q.y += b.y; Q.z += b.z; Q.w += b.w;
            }
            *(float4*)&g_ps[(size_t)bt * Xpad + x] = S;
            *(float4*)&g_pq[(size_t)bt * Xpad + x] = Q;
        }
    }
}

// ============================================================================
// kstats_final — reduce 32 partials -> BN scale/shift
// ============================================================================
__global__ __launch_bounds__(256) void kstats_final(
    const float* __restrict__ gamma, const float* __restrict__ beta)
{
    int x = blockIdx.x * 256 + threadIdx.x;
    if (x >= Xdim) return;
    float s = 0.f, q = 0.f;
    #pragma unroll
    for (int j = 0; j < NBT; j++) {
        s += g_ps[(size_t)j * Xpad + x];
        q += g_pq[(size_t)j * Xpad + x];
    }
    const float invB = 1.f / (float)Bdim;
    float mean = s * invB;
    float var  = q * invB - mean * mean;
    float inv  = rsqrtf(var + BN_EPS);
    float sc   = inv * gamma[x];
    g_scale[x] = sc;
    g_shift[x] = beta[x] - mean * sc;
}

// ============================================================================
// K3 — affine + softmax; online 2-phase, logits cached in smem, 1024 threads.
// ============================================================================
#define K3_SMEM (Xdim * 4)
#define K3_THREADS 1024

__global__ __launch_bounds__(K3_THREADS) void k3_softmax(float* __restrict__ outx)
{
    extern __shared__ float sa[];
    const int b = blockIdx.x;
    const int t = threadIdx.x;
    float4* row = (float4*)(outx + (size_t)b * Xdim);
    const float4* sc4 = (const float4*)g_scale;
    const float4* sh4 = (const float4*)g_shift;
    const int N4 = Xdim / 4;

    float m = -1e30f, s = 0.f;
    for (int i = t; i < N4; i += K3_THREADS) {
        float4 v = row[i], sc = sc4[i], sh = sh4[i];
        float4 a;
        a.x = fmaf(v.x, sc.x, sh.x);
        a.y = fmaf(v.y, sc.y, sh.y);
        a.z = fmaf(v.z, sc.z, sh.z);
        a.w = fmaf(v.w, sc.w, sh.w);
        *(float4*)&sa[i * 4] = a;
        float mv = fmaxf(fmaxf(a.x, a.y), fmaxf(a.z, a.w));
        float nm = fmaxf(m, mv);
        s = s * __expf(m - nm) + __expf(a.x - nm) + __expf(a.y - nm)
          + __expf(a.z - nm) + __expf(a.w - nm);
        m = nm;
    }
    #pragma unroll
    for (int o = 16; o; o >>= 1) {
        float mo = __shfl_xor_sync(0xFFFFFFFFu, m, o);
        float so = __shfl_xor_sync(0xFFFFFFFFu, s, o);
        float nm = fmaxf(m, mo);
        s = s * __expf(m - nm) + so * __expf(mo - nm);
        m = nm;
    }
    __shared__ float sm[32], ss[32];
    int w = t >> 5, l = t & 31;
    if (l == 0) { sm[w] = m; ss[w] = s; }
    __syncthreads();
    if (w == 0) {
        m = sm[l];
        s = ss[l];
        #pragma unroll
        for (int o = 16; o; o >>= 1) {
            float mo = __shfl_xor_sync(0xFFFFFFFFu, m, o);
            float so = __shfl_xor_sync(0xFFFFFFFFu, s, o);
            float nm = fmaxf(m, mo);
            s = s * __expf(m - nm) + so * __expf(mo - nm);
            m = nm;
        }
        if (l == 0) { sm[0] = m; ss[0] = s; }
    }
    __syncthreads();
    const float M = sm[0];
    const float invS = 1.f / ss[0];

    for (int i = t; i < N4; i += K3_THREADS) {
        float4 a = *(float4*)&sa[i * 4];
        float4 o;
        o.x = __expf(a.x - M) * invS;
        o.y = __expf(a.y - M) * invS;
        o.z = __expf(a.z - M) * invS;
        o.w = __expf(a.w - M) * invS;
        row[i] = o;
    }
}

// ============================================================================
extern "C" void kernel_launch(void* const* d_in, const int* in_sizes, int n_in,
                              void* d_out, int out_size)
{
    const float* z      = (const float*)d_in[0];
    const float* y      = (const float*)d_in[1];
    const float* Wmu    = (const float*)d_in[2];
    const float* bmu    = (const float*)d_in[3];
    const float* Wvar   = (const float*)d_in[4];
    const float* bvar   = (const float*)d_in[5];
    const float* Wg2    = (const float*)d_in[6];
    const float* styleL = (const float*)d_in[7];
    const float* styleR = (const float*)d_in[8];
    const float* gamma  = (const float*)d_in[9];
    const float* beta   = (const float*)d_in[10];

    float* out     = (float*)d_out;
    float* out_mu  = out;
    float* out_var = out + (size_t)Bdim * Zdim;
    float* outx    = out + (size_t)2 * Bdim * Zdim;

    cudaFuncSetAttribute(k1r_gemm, cudaFuncAttributeMaxDynamicSharedMemorySize, KR_SMEM);
    cudaFuncSetAttribute(k1_gemm, cudaFuncAttributeMaxDynamicSharedMemorySize, K1_SMEM);
    cudaFuncSetAttribute(k3_softmax, cudaFuncAttributeMaxDynamicSharedMemorySize, K3_SMEM);

    // one-time side stream + fork/join events (no device memory allocation;
    // identical captured work on every call)
    static cudaStream_t s2 = nullptr;
    static cudaEvent_t evFork = nullptr, evJoin = nullptr;
    if (s2 == nullptr) {
        cudaStreamCreateWithFlags(&s2, cudaStreamNonBlocking);
        cudaEventCreateWithFlags(&evFork, cudaEventDisableTiming);
        cudaEventCreateWithFlags(&evJoin, cudaEventDisableTiming);
    }

    dim3 g1(Bdim / 128, Xpad / 128);

    // ---- fork: k1r on side stream, splits+k0 on main stream ----
    cudaEventRecord(evFork, 0);
    cudaStreamWaitEvent(s2, evFork, 0);
    k1r_gemm<<<g1, 256, KR_SMEM, s2>>>(y, styleR);
    cudaEventRecord(evJoin, s2);

    ksplitW<<<WBLKS + Ydim, 256>>>(Wg2, Wmu, Wvar);
    k0_small<<<Bdim / 8, 256>>>(z, y, bmu, bvar, styleL, out_mu, out_var);

    // ---- join: k1 needs g_R (side) + splits/A (main) ----
    cudaStreamWaitEvent(0, evJoin, 0);
    k1_gemm<<<g1, 256, K1_SMEM>>>(outx);

    kstats_final<<<(Xdim + 255) / 256, 256>>>(gamma, beta);
    k3_softmax<<<Bdim, K3_THREADS, K3_SMEM>>>(outx);
}